// round 1
// baseline (speedup 1.0000x reference)
#include <cuda_runtime.h>

#define N_NODES 50000
#define N_EDGES 800000
#define IN_CH   100
#define HID     128
#define OUT_CH  47
#define ORIG    25000

// ---- scratch (device globals; no allocation allowed) ----
__device__ int   g_cnt [N_NODES];
__device__ int   g_fill[N_NODES];
__device__ int   g_off [N_NODES + 1];
__device__ int   g_adj [N_EDGES];
__device__ float g_agg1[(size_t)N_NODES * IN_CH];
__device__ float g_h   [(size_t)N_NODES * HID];
__device__ float g_g0  [(size_t)N_NODES * OUT_CH];

// ---- 1. zero counters ----
__global__ void k_zero() {
    int i = blockIdx.x * blockDim.x + threadIdx.x;
    if (i < N_NODES) { g_cnt[i] = 0; g_fill[i] = 0; }
}

// ---- 2. count in-degree ----
__global__ void k_count(const int* __restrict__ dst) {
    int i = blockIdx.x * blockDim.x + threadIdx.x;
    if (i < N_EDGES) atomicAdd(&g_cnt[dst[i]], 1);
}

// ---- 3. exclusive scan over 50000 counts (single block) ----
#define SCAN_T 1024
#define SCAN_CH ((N_NODES + SCAN_T - 1) / SCAN_T)
__global__ void k_scan() {
    __shared__ int s[SCAN_T];
    int t = threadIdx.x;
    int start = t * SCAN_CH;
    int end   = min(start + SCAN_CH, N_NODES);
    int sum = 0;
    for (int i = start; i < end; i++) sum += g_cnt[i];
    s[t] = sum;
    __syncthreads();
    for (int d = 1; d < SCAN_T; d <<= 1) {
        int v = (t >= d) ? s[t - d] : 0;
        __syncthreads();
        s[t] += v;
        __syncthreads();
    }
    int excl = s[t] - sum;
    for (int i = start; i < end; i++) {
        g_off[i] = excl;
        excl += g_cnt[i];
    }
    if (t == SCAN_T - 1) g_off[N_NODES] = excl;   // == N_EDGES
}

// ---- 4. fill CSR adjacency (src ids grouped by dst) ----
__global__ void k_fill(const int* __restrict__ src, const int* __restrict__ dst) {
    int i = blockIdx.x * blockDim.x + threadIdx.x;
    if (i < N_EDGES) {
        int d = dst[i];
        int p = atomicAdd(&g_fill[d], 1);
        g_adj[g_off[d] + p] = src[i];
    }
}

// ---- 5. layer-1 mean aggregation: agg1[i] = mean_{j in N(i)} x[j]  (warp/node) ----
__global__ void k_agg1(const float* __restrict__ x) {
    int w    = (blockIdx.x * blockDim.x + threadIdx.x) >> 5;
    int lane = threadIdx.x & 31;
    if (w >= N_NODES) return;
    int beg = g_off[w], end = g_off[w + 1];
    float4 acc = make_float4(0.f, 0.f, 0.f, 0.f);
    for (int e = beg; e < end; e++) {
        int s = g_adj[e];
        if (lane < IN_CH / 4) {
            float4 v = reinterpret_cast<const float4*>(x + (size_t)s * IN_CH)[lane];
            acc.x += v.x; acc.y += v.y; acc.z += v.z; acc.w += v.w;
        }
    }
    float inv = 1.f / fmaxf((float)(end - beg), 1.f);
    if (lane < IN_CH / 4) {
        acc.x *= inv; acc.y *= inv; acc.z *= inv; acc.w *= inv;
        reinterpret_cast<float4*>(g_agg1 + (size_t)w * IN_CH)[lane] = acc;
    }
}

// ---- 6. fused layer-1 GEMM: h = agg1 @ w1_l + b1_l + x @ w1_r   (8 rows/block) ----
__global__ void k_gemm1(const float* __restrict__ x,  const float* __restrict__ w1l,
                        const float* __restrict__ b1l, const float* __restrict__ w1r) {
    __shared__ float sa[8 * IN_CH];
    __shared__ float sx[8 * IN_CH];
    int tid = threadIdx.x;              // 128 threads = output column
    int r0  = blockIdx.x * 8;
    for (int i = tid; i < 8 * IN_CH; i += 128) {
        int r = i / IN_CH, k = i - r * IN_CH;
        int node = r0 + r;
        float va = 0.f, vx = 0.f;
        if (node < N_NODES) {
            va = g_agg1[(size_t)node * IN_CH + k];
            vx = x     [(size_t)node * IN_CH + k];
        }
        sa[i] = va; sx[i] = vx;
    }
    __syncthreads();
    float acc[8];
    float b = b1l[tid];
#pragma unroll
    for (int r = 0; r < 8; r++) acc[r] = b;
    for (int k = 0; k < IN_CH; k++) {
        float wl = w1l[k * HID + tid];
        float wr = w1r[k * HID + tid];
#pragma unroll
        for (int r = 0; r < 8; r++)
            acc[r] += sa[r * IN_CH + k] * wl + sx[r * IN_CH + k] * wr;
    }
#pragma unroll
    for (int r = 0; r < 8; r++) {
        int node = r0 + r;
        if (node < N_NODES) g_h[(size_t)node * HID + tid] = acc[r];
    }
}

// ---- 7. g0 = h @ w2_l  (16 rows/block, 64 threads, 47 active cols) ----
__global__ void k_gemm2(const float* __restrict__ w2l) {
    __shared__ float sh[16 * HID];
    int tid = threadIdx.x;              // 64
    int r0  = blockIdx.x * 16;
    for (int i = tid; i < 16 * HID; i += 64) {
        int r = i >> 7, k = i & 127;
        int node = r0 + r;
        sh[i] = (node < N_NODES) ? g_h[(size_t)node * HID + k] : 0.f;
    }
    __syncthreads();
    if (tid >= OUT_CH) return;
    float acc[16];
#pragma unroll
    for (int r = 0; r < 16; r++) acc[r] = 0.f;
    for (int k = 0; k < HID; k++) {
        float wv = w2l[k * OUT_CH + tid];
#pragma unroll
        for (int r = 0; r < 16; r++) acc[r] += sh[r * HID + k] * wv;
    }
#pragma unroll
    for (int r = 0; r < 16; r++) {
        int node = r0 + r;
        if (node < N_NODES) g_g0[(size_t)node * OUT_CH + tid] = acc[r];
    }
}

// ---- 8. final: out = log_softmax(mean(g0 over nbrs) + b2 + h @ w2_r)  for i < ORIG ----
// warp per node; lane owns cols {lane, lane+32} (second only if lane<15)
__global__ void k_final(const float* __restrict__ b2, const float* __restrict__ w2r,
                        float* __restrict__ out) {
    int w    = (blockIdx.x * blockDim.x + threadIdx.x) >> 5;
    int lane = threadIdx.x & 31;
    if (w >= ORIG) return;
    int beg = g_off[w], end = g_off[w + 1];
    float a0 = 0.f, a1 = 0.f;
    for (int e = beg; e < end; e++) {
        int s = g_adj[e];
        const float* row = g_g0 + (size_t)s * OUT_CH;
        a0 += row[lane];
        if (lane < OUT_CH - 32) a1 += row[32 + lane];
    }
    float inv = 1.f / fmaxf((float)(end - beg), 1.f);
    a0 *= inv; a1 *= inv;
    a0 += b2[lane];
    if (lane < OUT_CH - 32) a1 += b2[32 + lane];

    // + h[w] @ w2_r  via warp-broadcast of h
    const float* hrow = g_h + (size_t)w * HID;
    for (int kb = 0; kb < HID; kb += 32) {
        float hv = hrow[kb + lane];
#pragma unroll
        for (int j = 0; j < 32; j++) {
            float hk = __shfl_sync(0xffffffffu, hv, j);
            a0 += hk * w2r[(kb + j) * OUT_CH + lane];
            if (lane < OUT_CH - 32) a1 += hk * w2r[(kb + j) * OUT_CH + 32 + lane];
        }
    }

    // log_softmax over the 47 values held by the warp
    float m = a0;
    if (lane < OUT_CH - 32) m = fmaxf(m, a1);
#pragma unroll
    for (int o = 16; o > 0; o >>= 1) m = fmaxf(m, __shfl_xor_sync(0xffffffffu, m, o));
    float e0 = expf(a0 - m);
    float e1 = (lane < OUT_CH - 32) ? expf(a1 - m) : 0.f;
    float ss = e0 + e1;
#pragma unroll
    for (int o = 16; o > 0; o >>= 1) ss += __shfl_xor_sync(0xffffffffu, ss, o);
    float ls = m + logf(ss);
    out[(size_t)w * OUT_CH + lane] = a0 - ls;
    if (lane < OUT_CH - 32) out[(size_t)w * OUT_CH + 32 + lane] = a1 - ls;
}

extern "C" void kernel_launch(void* const* d_in, const int* in_sizes, int n_in,
                              void* d_out, int out_size) {
    const float* x   = (const float*)d_in[0];
    const int*   ei  = (const int*)  d_in[1];
    const int*   src = ei;
    const int*   dst = ei + N_EDGES;
    const float* w1l = (const float*)d_in[3];
    const float* b1l = (const float*)d_in[4];
    const float* w1r = (const float*)d_in[5];
    const float* w2l = (const float*)d_in[6];
    const float* b2l = (const float*)d_in[7];
    const float* w2r = (const float*)d_in[8];
    float* out = (float*)d_out;

    k_zero <<<(N_NODES + 255) / 256, 256>>>();
    k_count<<<(N_EDGES + 255) / 256, 256>>>(dst);
    k_scan <<<1, SCAN_T>>>();
    k_fill <<<(N_EDGES + 255) / 256, 256>>>(src, dst);
    k_agg1 <<<(N_NODES * 32 + 255) / 256, 256>>>(x);
    k_gemm1<<<(N_NODES + 7) / 8, 128>>>(x, w1l, b1l, w1r);
    k_gemm2<<<(N_NODES + 15) / 16, 64>>>(w2l);
    k_final<<<(ORIG * 32 + 255) / 256, 256>>>(b2l, w2r, out);
}

// round 2
// speedup vs baseline: 1.2106x; 1.2106x over previous
#include <cuda_runtime.h>

#define N_NODES 50000
#define N_EDGES 800000
#define IN_CH   100
#define HID     128
#define OUT_CH  47
#define OUT_P   48
#define ORIG    25000

typedef unsigned long long U64;

static __device__ __forceinline__ U64 fma2(U64 a, U64 b, U64 c) {
    U64 d;
    asm("fma.rn.f32x2 %0, %1, %2, %3;" : "=l"(d) : "l"(a), "l"(b), "l"(c));
    return d;
}
static __device__ __forceinline__ float pairsum(U64 v) {
    float2 f = *reinterpret_cast<float2*>(&v);
    return f.x + f.y;
}

// ---- scratch ----
__device__ int    g_cnt [N_NODES];
__device__ int    g_fill[N_NODES];
__device__ int    g_off [N_NODES + 1];
__device__ int    g_adj [N_EDGES];
__device__ float  g_agg1[(size_t)N_NODES * IN_CH];
__device__ float  g_h   [(size_t)N_NODES * HID];
__device__ float  g_g0  [(size_t)N_NODES * OUT_CH];
__device__ float  g_r0  [(size_t)ORIG * OUT_P];
__device__ float2 g_wp1l[50 * HID];     // [k2][col]  k pairs of w1_l
__device__ float2 g_wp1r[50 * HID];
__device__ float2 g_wp2l[64 * OUT_P];   // [k2][col]  (col 47 zero-padded)
__device__ float2 g_wp2r[64 * OUT_P];

// ---- 1. zero counters ----
__global__ void k_zero() {
    int i = blockIdx.x * blockDim.x + threadIdx.x;
    if (i < N_NODES) { g_cnt[i] = 0; g_fill[i] = 0; }
}

// ---- 2. count in-degree ----
__global__ void k_count(const int* __restrict__ dst) {
    int i = blockIdx.x * blockDim.x + threadIdx.x;
    if (i < N_EDGES) atomicAdd(&g_cnt[dst[i]], 1);
}

// ---- 3. exclusive scan (single block) ----
#define SCAN_T 1024
#define SCAN_CH ((N_NODES + SCAN_T - 1) / SCAN_T)
__global__ void k_scan() {
    __shared__ int s[SCAN_T];
    int t = threadIdx.x;
    int start = t * SCAN_CH;
    int end   = min(start + SCAN_CH, N_NODES);
    int sum = 0;
    for (int i = start; i < end; i++) sum += g_cnt[i];
    s[t] = sum;
    __syncthreads();
    for (int d = 1; d < SCAN_T; d <<= 1) {
        int v = (t >= d) ? s[t - d] : 0;
        __syncthreads();
        s[t] += v;
        __syncthreads();
    }
    int excl = s[t] - sum;
    for (int i = start; i < end; i++) { g_off[i] = excl; excl += g_cnt[i]; }
    if (t == SCAN_T - 1) g_off[N_NODES] = excl;
}

// ---- 4. fill CSR ----
__global__ void k_fill(const int* __restrict__ src, const int* __restrict__ dst) {
    int i = blockIdx.x * blockDim.x + threadIdx.x;
    if (i < N_EDGES) {
        int d = dst[i];
        int p = atomicAdd(&g_fill[d], 1);
        g_adj[g_off[d] + p] = src[i];
    }
}

// ---- 5. prepack weights into k-pair float2 layout ----
__global__ void k_prepack(const float* __restrict__ w1l, const float* __restrict__ w1r,
                          const float* __restrict__ w2l, const float* __restrict__ w2r) {
    int i = blockIdx.x * blockDim.x + threadIdx.x;
    if (i < 50 * HID) {
        int k2 = i / HID, c = i % HID;
        g_wp1l[i] = make_float2(w1l[(2 * k2) * HID + c], w1l[(2 * k2 + 1) * HID + c]);
        g_wp1r[i] = make_float2(w1r[(2 * k2) * HID + c], w1r[(2 * k2 + 1) * HID + c]);
    }
    if (i < 64 * OUT_P) {
        int k2 = i / OUT_P, c = i % OUT_P;
        float l0 = 0.f, l1 = 0.f, r0 = 0.f, r1 = 0.f;
        if (c < OUT_CH) {
            l0 = w2l[(2 * k2) * OUT_CH + c]; l1 = w2l[(2 * k2 + 1) * OUT_CH + c];
            r0 = w2r[(2 * k2) * OUT_CH + c]; r1 = w2r[(2 * k2 + 1) * OUT_CH + c];
        }
        g_wp2l[i] = make_float2(l0, l1);
        g_wp2r[i] = make_float2(r0, r1);
    }
}

// ---- 6. layer-1 mean aggregation (warp/node) ----
__global__ void k_agg1(const float* __restrict__ x) {
    int w    = (blockIdx.x * blockDim.x + threadIdx.x) >> 5;
    int lane = threadIdx.x & 31;
    if (w >= N_NODES) return;
    int beg = g_off[w], end = g_off[w + 1];
    float4 acc = make_float4(0.f, 0.f, 0.f, 0.f);
    for (int e = beg; e < end; e++) {
        int s = g_adj[e];
        if (lane < IN_CH / 4) {
            float4 v = reinterpret_cast<const float4*>(x + (size_t)s * IN_CH)[lane];
            acc.x += v.x; acc.y += v.y; acc.z += v.z; acc.w += v.w;
        }
    }
    float inv = 1.f / fmaxf((float)(end - beg), 1.f);
    if (lane < IN_CH / 4) {
        acc.x *= inv; acc.y *= inv; acc.z *= inv; acc.w *= inv;
        reinterpret_cast<float4*>(g_agg1 + (size_t)w * IN_CH)[lane] = acc;
    }
}

// ---- 7. layer-1 GEMM (f32x2, k-pair accumulation): h = agg1@w1l + x@w1r + b1 ----
// 128 threads, 32 rows/block.  tx = col-group (4 cols), ty = row-group (8 rows).
__global__ void __launch_bounds__(128) k_gemm1(const float* __restrict__ x,
                                               const float* __restrict__ b1l) {
    __shared__ float sa[32 * IN_CH];
    __shared__ float sx[32 * IN_CH];
    int tid = threadIdx.x;
    int tx = tid & 31, ty = tid >> 5;
    int row0 = blockIdx.x * 32;
    // stage 32 rows of agg1 and x (25 float4 per row)
    for (int i = tid; i < 32 * 25; i += 128) {
        int r = i / 25, c4 = i % 25;
        int node = row0 + r;
        float4 va = make_float4(0.f, 0.f, 0.f, 0.f), vx = va;
        if (node < N_NODES) {
            va = reinterpret_cast<const float4*>(g_agg1 + (size_t)node * IN_CH)[c4];
            vx = reinterpret_cast<const float4*>(x + (size_t)node * IN_CH)[c4];
        }
        reinterpret_cast<float4*>(sa + r * IN_CH)[c4] = va;
        reinterpret_cast<float4*>(sx + r * IN_CH)[c4] = vx;
    }
    __syncthreads();

    U64 acc[8][4];
#pragma unroll
    for (int r = 0; r < 8; r++)
#pragma unroll
        for (int c = 0; c < 4; c++) acc[r][c] = 0ull;

#pragma unroll 1
    for (int kk = 0; kk < 25; kk++) {            // 4 k per iter = 2 k-pairs
        const ulonglong2* wl0 = reinterpret_cast<const ulonglong2*>(g_wp1l + (2 * kk) * HID + 4 * tx);
        const ulonglong2* wl1 = reinterpret_cast<const ulonglong2*>(g_wp1l + (2 * kk + 1) * HID + 4 * tx);
        const ulonglong2* wr0 = reinterpret_cast<const ulonglong2*>(g_wp1r + (2 * kk) * HID + 4 * tx);
        const ulonglong2* wr1 = reinterpret_cast<const ulonglong2*>(g_wp1r + (2 * kk + 1) * HID + 4 * tx);
        ulonglong2 l0 = wl0[0], l0b = wl0[1];    // pair0: cols c0,c1 / c2,c3
        ulonglong2 l1 = wl1[0], l1b = wl1[1];    // pair1
        ulonglong2 r0 = wr0[0], r0b = wr0[1];
        ulonglong2 r1 = wr1[0], r1b = wr1[1];
        U64 wl2[2][4] = {{l0.x, l0.y, l0b.x, l0b.y}, {l1.x, l1.y, l1b.x, l1b.y}};
        U64 wr2[2][4] = {{r0.x, r0.y, r0b.x, r0b.y}, {r1.x, r1.y, r1b.x, r1b.y}};
#pragma unroll
        for (int r = 0; r < 8; r++) {
            int row = ty * 8 + r;
            ulonglong2 av = *reinterpret_cast<const ulonglong2*>(sa + row * IN_CH + 4 * kk);
            ulonglong2 xv = *reinterpret_cast<const ulonglong2*>(sx + row * IN_CH + 4 * kk);
#pragma unroll
            for (int c = 0; c < 4; c++) {
                acc[r][c] = fma2(av.x, wl2[0][c], acc[r][c]);
                acc[r][c] = fma2(av.y, wl2[1][c], acc[r][c]);
                acc[r][c] = fma2(xv.x, wr2[0][c], acc[r][c]);
                acc[r][c] = fma2(xv.y, wr2[1][c], acc[r][c]);
            }
        }
    }
    float4 bias = reinterpret_cast<const float4*>(b1l)[tx];
#pragma unroll
    for (int r = 0; r < 8; r++) {
        int node = row0 + ty * 8 + r;
        if (node < N_NODES) {
            float4 o;
            o.x = pairsum(acc[r][0]) + bias.x;
            o.y = pairsum(acc[r][1]) + bias.y;
            o.z = pairsum(acc[r][2]) + bias.z;
            o.w = pairsum(acc[r][3]) + bias.w;
            reinterpret_cast<float4*>(g_h + (size_t)node * HID)[tx] = o;
        }
    }
}

// ---- 8. layer-2 GEMMs: g0 = h@w2l (all rows); r0 = h@w2r + b2 (rows < ORIG) ----
// 128 threads: tx = tid%64 (col, <48 active), ty = tid/64 (16 rows each); 32 rows/block.
__global__ void __launch_bounds__(128) k_gemm2(const float* __restrict__ b2) {
    __shared__ float sh[32 * HID];
    int tid = threadIdx.x;
    int tx = tid & 63, ty = tid >> 6;
    int row0 = blockIdx.x * 32;
    for (int i = tid; i < 32 * 32; i += 128) {    // 32 rows x 32 float4
        int r = i >> 5, c4 = i & 31;
        int node = row0 + r;
        float4 v = make_float4(0.f, 0.f, 0.f, 0.f);
        if (node < N_NODES) v = reinterpret_cast<const float4*>(g_h + (size_t)node * HID)[c4];
        reinterpret_cast<float4*>(sh + r * HID)[c4] = v;
    }
    __syncthreads();
    if (tx >= OUT_P) return;
    bool do_r = (row0 < ORIG);
    int col = tx;
    U64 accg[16], accr[16];
#pragma unroll
    for (int r = 0; r < 16; r++) { accg[r] = 0ull; accr[r] = 0ull; }

#pragma unroll 1
    for (int kk = 0; kk < 32; kk++) {             // 4 k per iter = 2 k-pairs
        float2 wg0f = g_wp2l[(2 * kk) * OUT_P + col];
        float2 wg1f = g_wp2l[(2 * kk + 1) * OUT_P + col];
        U64 wg0 = *reinterpret_cast<U64*>(&wg0f);
        U64 wg1 = *reinterpret_cast<U64*>(&wg1f);
        U64 wr0 = 0ull, wr1 = 0ull;
        if (do_r) {
            float2 a = g_wp2r[(2 * kk) * OUT_P + col];
            float2 b = g_wp2r[(2 * kk + 1) * OUT_P + col];
            wr0 = *reinterpret_cast<U64*>(&a);
            wr1 = *reinterpret_cast<U64*>(&b);
        }
#pragma unroll
        for (int r = 0; r < 16; r++) {
            int row = ty * 16 + r;
            ulonglong2 hv = *reinterpret_cast<const ulonglong2*>(sh + row * HID + 4 * kk);
            accg[r] = fma2(hv.x, wg0, accg[r]);
            accg[r] = fma2(hv.y, wg1, accg[r]);
            if (do_r) {
                accr[r] = fma2(hv.x, wr0, accr[r]);
                accr[r] = fma2(hv.y, wr1, accr[r]);
            }
        }
    }
    float bv = (col < OUT_CH) ? b2[col] : 0.f;
#pragma unroll
    for (int r = 0; r < 16; r++) {
        int node = row0 + ty * 16 + r;
        if (node < N_NODES && col < OUT_CH)
            g_g0[(size_t)node * OUT_CH + col] = pairsum(accg[r]);
        if (node < ORIG)
            g_r0[(size_t)node * OUT_P + col] = pairsum(accr[r]) + bv;
    }
}

// ---- 9. final: out = log_softmax(mean_nbr(g0) + r0)  for i < ORIG ----
__global__ void k_final(float* __restrict__ out) {
    int w    = (blockIdx.x * blockDim.x + threadIdx.x) >> 5;
    int lane = threadIdx.x & 31;
    if (w >= ORIG) return;
    int beg = g_off[w], end = g_off[w + 1];
    float a0 = 0.f, a1 = 0.f;
    for (int e = beg; e < end; e++) {
        int s = g_adj[e];
        const float* row = g_g0 + (size_t)s * OUT_CH;
        a0 += __ldg(row + lane);
        if (lane < OUT_CH - 32) a1 += __ldg(row + 32 + lane);
    }
    float inv = 1.f / fmaxf((float)(end - beg), 1.f);
    const float* r0row = g_r0 + (size_t)w * OUT_P;
    a0 = a0 * inv + r0row[lane];
    if (lane < OUT_CH - 32) a1 = a1 * inv + r0row[32 + lane];

    float m = a0;
    if (lane < OUT_CH - 32) m = fmaxf(m, a1);
#pragma unroll
    for (int o = 16; o > 0; o >>= 1) m = fmaxf(m, __shfl_xor_sync(0xffffffffu, m, o));
    float e0 = expf(a0 - m);
    float e1 = (lane < OUT_CH - 32) ? expf(a1 - m) : 0.f;
    float ss = e0 + e1;
#pragma unroll
    for (int o = 16; o > 0; o >>= 1) ss += __shfl_xor_sync(0xffffffffu, ss, o);
    float ls = m + logf(ss);
    out[(size_t)w * OUT_CH + lane] = a0 - ls;
    if (lane < OUT_CH - 32) out[(size_t)w * OUT_CH + 32 + lane] = a1 - ls;
}

extern "C" void kernel_launch(void* const* d_in, const int* in_sizes, int n_in,
                              void* d_out, int out_size) {
    const float* x   = (const float*)d_in[0];
    const int*   ei  = (const int*)  d_in[1];
    const int*   src = ei;
    const int*   dst = ei + N_EDGES;
    const float* w1l = (const float*)d_in[3];
    const float* b1l = (const float*)d_in[4];
    const float* w1r = (const float*)d_in[5];
    const float* w2l = (const float*)d_in[6];
    const float* b2l = (const float*)d_in[7];
    const float* w2r = (const float*)d_in[8];
    float* out = (float*)d_out;

    k_zero   <<<(N_NODES + 255) / 256, 256>>>();
    k_prepack<<<(50 * HID + 255) / 256, 256>>>(w1l, w1r, w2l, w2r);
    k_count  <<<(N_EDGES + 255) / 256, 256>>>(dst);
    k_scan   <<<1, SCAN_T>>>();
    k_fill   <<<(N_EDGES + 255) / 256, 256>>>(src, dst);
    k_agg1   <<<(N_NODES * 32 + 255) / 256, 256>>>(x);
    k_gemm1  <<<(N_NODES + 31) / 32, 128>>>(x, b1l);
    k_gemm2  <<<(N_NODES + 31) / 32, 128>>>(b2l);
    k_final  <<<(ORIG * 32 + 255) / 256, 256>>>(out);
}

// round 3
// speedup vs baseline: 1.4626x; 1.2081x over previous
#include <cuda_runtime.h>

#define N_NODES 50000
#define N_EDGES 800000
#define IN_CH   100
#define HID     128
#define OUT_CH  47
#define OUT_P   48
#define ORIG    25000

#define SCAN_BS   256
#define SCAN_NB   ((N_NODES + SCAN_BS - 1) / SCAN_BS)   // 196

typedef unsigned long long U64;

static __device__ __forceinline__ U64 fma2(U64 a, U64 b, U64 c) {
    U64 d;
    asm("fma.rn.f32x2 %0, %1, %2, %3;" : "=l"(d) : "l"(a), "l"(b), "l"(c));
    return d;
}
static __device__ __forceinline__ float pairsum(U64 v) {
    float2 f = *reinterpret_cast<float2*>(&v);
    return f.x + f.y;
}

// ---- scratch ----
__device__ int    g_cnt [N_NODES];
__device__ int    g_fill[N_NODES];
__device__ int    g_off [N_NODES + 1];
__device__ int    g_bsum[SCAN_NB];
__device__ int    g_boff[SCAN_NB];
__device__ int    g_adj [N_EDGES];
__device__ float  g_agg1[(size_t)N_NODES * IN_CH];
__device__ float  g_h   [(size_t)N_NODES * HID];
__device__ float  g_g0  [(size_t)N_NODES * OUT_CH];
__device__ float  g_r0  [(size_t)ORIG * OUT_P];
__device__ float2 g_wp1l[50 * HID];
__device__ float2 g_wp1r[50 * HID];
__device__ float2 g_wp2l[64 * OUT_P];
__device__ float2 g_wp2r[64 * OUT_P];

// ---- 1. zero counters ----
__global__ void k_zero() {
    int i = blockIdx.x * blockDim.x + threadIdx.x;
    if (i < N_NODES) { g_cnt[i] = 0; g_fill[i] = 0; }
}

// ---- 2. count in-degree ----
__global__ void k_count(const int* __restrict__ dst) {
    int i = blockIdx.x * blockDim.x + threadIdx.x;
    if (i < N_EDGES) atomicAdd(&g_cnt[dst[i]], 1);
}

// ---- 3a. per-block sums of counts ----
__global__ void k_blocksum() {
    __shared__ int s[SCAN_BS];
    int i = blockIdx.x * SCAN_BS + threadIdx.x;
    int v = (i < N_NODES) ? g_cnt[i] : 0;
    s[threadIdx.x] = v;
    __syncthreads();
    for (int d = SCAN_BS / 2; d > 0; d >>= 1) {
        if (threadIdx.x < d) s[threadIdx.x] += s[threadIdx.x + d];
        __syncthreads();
    }
    if (threadIdx.x == 0) g_bsum[blockIdx.x] = s[0];
}

// ---- 3b. scan the block sums (single block, 256 threads) ----
__global__ void k_scanb() {
    __shared__ int s[SCAN_BS];
    int t = threadIdx.x;
    int v = (t < SCAN_NB) ? g_bsum[t] : 0;
    s[t] = v;
    __syncthreads();
    for (int d = 1; d < SCAN_BS; d <<= 1) {
        int u = (t >= d) ? s[t - d] : 0;
        __syncthreads();
        s[t] += u;
        __syncthreads();
    }
    if (t < SCAN_NB) g_boff[t] = s[t] - v;           // exclusive
    if (t == SCAN_NB - 1) g_off[N_NODES] = s[t];     // total = N_EDGES
}

// ---- 3c. local exclusive scan + block offset -> g_off ----
__global__ void k_offsets() {
    __shared__ int s[SCAN_BS];
    int t = threadIdx.x;
    int i = blockIdx.x * SCAN_BS + t;
    int v = (i < N_NODES) ? g_cnt[i] : 0;
    s[t] = v;
    __syncthreads();
    for (int d = 1; d < SCAN_BS; d <<= 1) {
        int u = (t >= d) ? s[t - d] : 0;
        __syncthreads();
        s[t] += u;
        __syncthreads();
    }
    if (i < N_NODES) g_off[i] = g_boff[blockIdx.x] + s[t] - v;
}

// ---- 4. fill CSR ----
__global__ void k_fill(const int* __restrict__ src, const int* __restrict__ dst) {
    int i = blockIdx.x * blockDim.x + threadIdx.x;
    if (i < N_EDGES) {
        int d = dst[i];
        int p = atomicAdd(&g_fill[d], 1);
        g_adj[g_off[d] + p] = src[i];
    }
}

// ---- 5. prepack weights into k-pair float2 layout ----
__global__ void k_prepack(const float* __restrict__ w1l, const float* __restrict__ w1r,
                          const float* __restrict__ w2l, const float* __restrict__ w2r) {
    int i = blockIdx.x * blockDim.x + threadIdx.x;
    if (i < 50 * HID) {
        int k2 = i / HID, c = i % HID;
        g_wp1l[i] = make_float2(w1l[(2 * k2) * HID + c], w1l[(2 * k2 + 1) * HID + c]);
        g_wp1r[i] = make_float2(w1r[(2 * k2) * HID + c], w1r[(2 * k2 + 1) * HID + c]);
    }
    if (i < 64 * OUT_P) {
        int k2 = i / OUT_P, c = i % OUT_P;
        float l0 = 0.f, l1 = 0.f, r0 = 0.f, r1 = 0.f;
        if (c < OUT_CH) {
            l0 = w2l[(2 * k2) * OUT_CH + c]; l1 = w2l[(2 * k2 + 1) * OUT_CH + c];
            r0 = w2r[(2 * k2) * OUT_CH + c]; r1 = w2r[(2 * k2 + 1) * OUT_CH + c];
        }
        g_wp2l[i] = make_float2(l0, l1);
        g_wp2r[i] = make_float2(r0, r1);
    }
}

// ---- 6. layer-1 mean aggregation (warp/node) ----
__global__ void k_agg1(const float* __restrict__ x) {
    int w    = (blockIdx.x * blockDim.x + threadIdx.x) >> 5;
    int lane = threadIdx.x & 31;
    if (w >= N_NODES) return;
    int beg = g_off[w], end = g_off[w + 1];
    float4 acc = make_float4(0.f, 0.f, 0.f, 0.f);
    for (int e = beg; e < end; e++) {
        int s = g_adj[e];
        if (lane < IN_CH / 4) {
            float4 v = reinterpret_cast<const float4*>(x + (size_t)s * IN_CH)[lane];
            acc.x += v.x; acc.y += v.y; acc.z += v.z; acc.w += v.w;
        }
    }
    float inv = 1.f / fmaxf((float)(end - beg), 1.f);
    if (lane < IN_CH / 4) {
        acc.x *= inv; acc.y *= inv; acc.z *= inv; acc.w *= inv;
        reinterpret_cast<float4*>(g_agg1 + (size_t)w * IN_CH)[lane] = acc;
    }
}

// ---- 7. layer-1 GEMM (f32x2): h = agg1@w1l + x@w1r + b1 ----
__global__ void __launch_bounds__(128) k_gemm1(const float* __restrict__ x,
                                               const float* __restrict__ b1l) {
    __shared__ float sa[32 * IN_CH];
    __shared__ float sx[32 * IN_CH];
    int tid = threadIdx.x;
    int tx = tid & 31, ty = tid >> 5;
    int row0 = blockIdx.x * 32;
    for (int i = tid; i < 32 * 25; i += 128) {
        int r = i / 25, c4 = i % 25;
        int node = row0 + r;
        float4 va = make_float4(0.f, 0.f, 0.f, 0.f), vx = va;
        if (node < N_NODES) {
            va = reinterpret_cast<const float4*>(g_agg1 + (size_t)node * IN_CH)[c4];
            vx = reinterpret_cast<const float4*>(x + (size_t)node * IN_CH)[c4];
        }
        reinterpret_cast<float4*>(sa + r * IN_CH)[c4] = va;
        reinterpret_cast<float4*>(sx + r * IN_CH)[c4] = vx;
    }
    __syncthreads();

    U64 acc[8][4];
#pragma unroll
    for (int r = 0; r < 8; r++)
#pragma unroll
        for (int c = 0; c < 4; c++) acc[r][c] = 0ull;

#pragma unroll 1
    for (int kk = 0; kk < 25; kk++) {
        const ulonglong2* wl0 = reinterpret_cast<const ulonglong2*>(g_wp1l + (2 * kk) * HID + 4 * tx);
        const ulonglong2* wl1 = reinterpret_cast<const ulonglong2*>(g_wp1l + (2 * kk + 1) * HID + 4 * tx);
        const ulonglong2* wr0 = reinterpret_cast<const ulonglong2*>(g_wp1r + (2 * kk) * HID + 4 * tx);
        const ulonglong2* wr1 = reinterpret_cast<const ulonglong2*>(g_wp1r + (2 * kk + 1) * HID + 4 * tx);
        ulonglong2 l0 = wl0[0], l0b = wl0[1];
        ulonglong2 l1 = wl1[0], l1b = wl1[1];
        ulonglong2 r0 = wr0[0], r0b = wr0[1];
        ulonglong2 r1 = wr1[0], r1b = wr1[1];
        U64 wl2[2][4] = {{l0.x, l0.y, l0b.x, l0b.y}, {l1.x, l1.y, l1b.x, l1b.y}};
        U64 wr2[2][4] = {{r0.x, r0.y, r0b.x, r0b.y}, {r1.x, r1.y, r1b.x, r1b.y}};
#pragma unroll
        for (int r = 0; r < 8; r++) {
            int row = ty * 8 + r;
            ulonglong2 av = *reinterpret_cast<const ulonglong2*>(sa + row * IN_CH + 4 * kk);
            ulonglong2 xv = *reinterpret_cast<const ulonglong2*>(sx + row * IN_CH + 4 * kk);
#pragma unroll
            for (int c = 0; c < 4; c++) {
                acc[r][c] = fma2(av.x, wl2[0][c], acc[r][c]);
                acc[r][c] = fma2(av.y, wl2[1][c], acc[r][c]);
                acc[r][c] = fma2(xv.x, wr2[0][c], acc[r][c]);
                acc[r][c] = fma2(xv.y, wr2[1][c], acc[r][c]);
            }
        }
    }
    float4 bias = reinterpret_cast<const float4*>(b1l)[tx];
#pragma unroll
    for (int r = 0; r < 8; r++) {
        int node = row0 + ty * 8 + r;
        if (node < N_NODES) {
            float4 o;
            o.x = pairsum(acc[r][0]) + bias.x;
            o.y = pairsum(acc[r][1]) + bias.y;
            o.z = pairsum(acc[r][2]) + bias.z;
            o.w = pairsum(acc[r][3]) + bias.w;
            reinterpret_cast<float4*>(g_h + (size_t)node * HID)[tx] = o;
        }
    }
}

// ---- 8. layer-2 GEMMs: g0 = h@w2l (all rows); r0 = h@w2r + b2 (rows < ORIG) ----
__global__ void __launch_bounds__(128) k_gemm2(const float* __restrict__ b2) {
    __shared__ float sh[32 * HID];
    int tid = threadIdx.x;
    int tx = tid & 63, ty = tid >> 6;
    int row0 = blockIdx.x * 32;
    for (int i = tid; i < 32 * 32; i += 128) {
        int r = i >> 5, c4 = i & 31;
        int node = row0 + r;
        float4 v = make_float4(0.f, 0.f, 0.f, 0.f);
        if (node < N_NODES) v = reinterpret_cast<const float4*>(g_h + (size_t)node * HID)[c4];
        reinterpret_cast<float4*>(sh + r * HID)[c4] = v;
    }
    __syncthreads();
    if (tx >= OUT_P) return;
    bool do_r = (row0 < ORIG);
    int col = tx;
    U64 accg[16], accr[16];
#pragma unroll
    for (int r = 0; r < 16; r++) { accg[r] = 0ull; accr[r] = 0ull; }

#pragma unroll 1
    for (int kk = 0; kk < 32; kk++) {
        float2 wg0f = g_wp2l[(2 * kk) * OUT_P + col];
        float2 wg1f = g_wp2l[(2 * kk + 1) * OUT_P + col];
        U64 wg0 = *reinterpret_cast<U64*>(&wg0f);
        U64 wg1 = *reinterpret_cast<U64*>(&wg1f);
        U64 wr0 = 0ull, wr1 = 0ull;
        if (do_r) {
            float2 a = g_wp2r[(2 * kk) * OUT_P + col];
            float2 b = g_wp2r[(2 * kk + 1) * OUT_P + col];
            wr0 = *reinterpret_cast<U64*>(&a);
            wr1 = *reinterpret_cast<U64*>(&b);
        }
#pragma unroll
        for (int r = 0; r < 16; r++) {
            int row = ty * 16 + r;
            ulonglong2 hv = *reinterpret_cast<const ulonglong2*>(sh + row * HID + 4 * kk);
            accg[r] = fma2(hv.x, wg0, accg[r]);
            accg[r] = fma2(hv.y, wg1, accg[r]);
            if (do_r) {
                accr[r] = fma2(hv.x, wr0, accr[r]);
                accr[r] = fma2(hv.y, wr1, accr[r]);
            }
        }
    }
    float bv = (col < OUT_CH) ? b2[col] : 0.f;
#pragma unroll
    for (int r = 0; r < 16; r++) {
        int node = row0 + ty * 16 + r;
        if (node < N_NODES && col < OUT_CH)
            g_g0[(size_t)node * OUT_CH + col] = pairsum(accg[r]);
        if (node < ORIG)
            g_r0[(size_t)node * OUT_P + col] = pairsum(accr[r]) + bv;
    }
}

// ---- 9. final: out = log_softmax(mean_nbr(g0) + r0)  for i < ORIG ----
__global__ void k_final(float* __restrict__ out) {
    int w    = (blockIdx.x * blockDim.x + threadIdx.x) >> 5;
    int lane = threadIdx.x & 31;
    if (w >= ORIG) return;
    int beg = g_off[w], end = g_off[w + 1];
    float a0 = 0.f, a1 = 0.f;
    for (int e = beg; e < end; e++) {
        int s = g_adj[e];
        const float* row = g_g0 + (size_t)s * OUT_CH;
        a0 += __ldg(row + lane);
        if (lane < OUT_CH - 32) a1 += __ldg(row + 32 + lane);
    }
    float inv = 1.f / fmaxf((float)(end - beg), 1.f);
    const float* r0row = g_r0 + (size_t)w * OUT_P;
    a0 = a0 * inv + r0row[lane];
    if (lane < OUT_CH - 32) a1 = a1 * inv + r0row[32 + lane];

    float m = a0;
    if (lane < OUT_CH - 32) m = fmaxf(m, a1);
#pragma unroll
    for (int o = 16; o > 0; o >>= 1) m = fmaxf(m, __shfl_xor_sync(0xffffffffu, m, o));
    float e0 = expf(a0 - m);
    float e1 = (lane < OUT_CH - 32) ? expf(a1 - m) : 0.f;
    float ss = e0 + e1;
#pragma unroll
    for (int o = 16; o > 0; o >>= 1) ss += __shfl_xor_sync(0xffffffffu, ss, o);
    float ls = m + logf(ss);
    out[(size_t)w * OUT_CH + lane] = a0 - ls;
    if (lane < OUT_CH - 32) out[(size_t)w * OUT_CH + 32 + lane] = a1 - ls;
}

extern "C" void kernel_launch(void* const* d_in, const int* in_sizes, int n_in,
                              void* d_out, int out_size) {
    const float* x   = (const float*)d_in[0];
    const int*   ei  = (const int*)  d_in[1];
    const int*   src = ei;
    const int*   dst = ei + N_EDGES;
    const float* w1l = (const float*)d_in[3];
    const float* b1l = (const float*)d_in[4];
    const float* w1r = (const float*)d_in[5];
    const float* w2l = (const float*)d_in[6];
    const float* b2l = (const float*)d_in[7];
    const float* w2r = (const float*)d_in[8];
    float* out = (float*)d_out;

    k_zero    <<<(N_NODES + 255) / 256, 256>>>();
    k_prepack <<<(50 * HID + 255) / 256, 256>>>(w1l, w1r, w2l, w2r);
    k_count   <<<(N_EDGES + 255) / 256, 256>>>(dst);
    k_blocksum<<<SCAN_NB, SCAN_BS>>>();
    k_scanb   <<<1, SCAN_BS>>>();
    k_offsets <<<SCAN_NB, SCAN_BS>>>();
    k_fill    <<<(N_EDGES + 255) / 256, 256>>>(src, dst);
    k_agg1    <<<(N_NODES * 32 + 255) / 256, 256>>>(x);
    k_gemm1   <<<(N_NODES + 31) / 32, 128>>>(x, b1l);
    k_gemm2   <<<(N_NODES + 31) / 32, 128>>>(b2l);
    k_final   <<<(ORIG * 32 + 255) / 256, 256>>>(out);
}